// round 14
// baseline (speedup 1.0000x reference)
#include <cuda_runtime.h>
#include <cuda_fp16.h>
#include <math.h>

#define NMAX 50048   // 391*128 padded so GEMM tile reads stay in-bounds
#define EMAX 500000

// ---------------- static scratch (zero-initialized at load; every replay
// restores g_cnt=0 / g_total=0 at its end, so graph replays are deterministic) --
__device__ __half g_xagg1[(size_t)NMAX * 1024];  // L1 per-(dst,rel) mean, fp16
__device__ __half g_xagg2[(size_t)NMAX * 1024];  // L2 per-(dst,rel) mean, fp16
__device__ __half g_xf[(size_t)NMAX * 128];      // L1 root input, fp16
__device__ __half g_hf[(size_t)NMAX * 128];      // relu(h), fp16
__device__ __half g_wb1[128 * 1152];             // L1 stacked W, fp16
__device__ __half g_wb2[64 * 1152];              // L2 stacked W, fp16
__device__ int   g_cnt[NMAX * 8];
__device__ int   g_off8[NMAX * 8];               // fill cursor (start -> end)
__device__ int2  g_meta[NMAX * 8];               // (start, count) — one 8B load
__device__ int   g_epack[EMAX];
__device__ int   g_total;

// ---------------- helpers ----------------
__device__ __forceinline__ unsigned smem_u32(const void* p) {
    unsigned a;
    asm("{ .reg .u64 t; cvta.to.shared.u64 t, %1; cvt.u32.u64 %0, t; }"
        : "=r"(a) : "l"(p));
    return a;
}
__device__ __forceinline__ unsigned lds32(unsigned a) {
    unsigned v;
    asm volatile("ld.shared.b32 %0, [%1];" : "=r"(v) : "r"(a));
    return v;
}
__device__ __forceinline__ void cp16(unsigned dst, const void* src) {
    asm volatile("cp.async.cg.shared.global [%0], [%1], 16;"
                 :: "r"(dst), "l"(src) : "memory");
}
#define CP_COMMIT() asm volatile("cp.async.commit_group;" ::: "memory")
#define CP_WAIT(n)  asm volatile("cp.async.wait_group %0;" :: "n"(n) : "memory")

__device__ __forceinline__ void mma_fp16(float* c, const unsigned* a, const unsigned* b) {
    asm volatile("mma.sync.aligned.m16n8k16.row.col.f32.f16.f16.f32 "
                 "{%0,%1,%2,%3}, {%4,%5,%6,%7}, {%8,%9}, {%0,%1,%2,%3};"
                 : "+f"(c[0]), "+f"(c[1]), "+f"(c[2]), "+f"(c[3])
                 : "r"(a[0]), "r"(a[1]), "r"(a[2]), "r"(a[3]),
                   "r"(b[0]), "r"(b[1]));
}

// block-local index dtype detect: int64 (LE) => odd 32-bit words all zero over
// 256 samples; int32 => some nonzero. Values are node ids < 50000.
__device__ __forceinline__ bool block_detect_idx64(const int* ei32) {
    __shared__ int any;
    if (threadIdx.x == 0) any = 0;
    __syncthreads();
    if (threadIdx.x < 256 && ei32[2 * threadIdx.x + 1] != 0) atomicOr(&any, 1);
    __syncthreads();
    return any == 0;
}

// ---------------- launch 1: count + conv1 + W pack (independent block ranges) --
__global__ void __launch_bounds__(256)
stage1_kernel(const void* __restrict__ ei, const void* __restrict__ et,
              const float* __restrict__ x,
              const float* __restrict__ W1, const float* __restrict__ root1,
              const float* __restrict__ W2, const float* __restrict__ root2,
              int E, int M) {
    const int CNT  = (E + 255) / 256;
    const int CONV = (M * 32 + 255) / 256;
    int b = blockIdx.x;

    if (b < CNT) {
        bool idx64 = block_detect_idx64((const int*)ei);
        int e = b * 256 + threadIdx.x;
        if (e < E) {
            int dst, r;
            if (idx64) {
                dst = (int)((const long long*)ei)[(long long)E + e];
                r   = (int)((const long long*)et)[e];
            } else {
                dst = ((const int*)ei)[E + e];
                r   = ((const int*)et)[e];
            }
            if ((unsigned)dst < 50000u && (unsigned)r < 8u)
                atomicAdd(&g_cnt[dst * 8 + r], 1);
        }
    } else if (b < CNT + CONV) {
        int i = (b - CNT) * 256 + threadIdx.x;
        if (i >= M * 32) return;
        float4 v = ((const float4*)x)[i];
        __half2* d = (__half2*)(g_xf + (size_t)i * 4);
        d[0] = __floats2half2_rn(v.x, v.y);
        d[1] = __floats2half2_rn(v.z, v.w);
    } else {
        int idx = (b - CNT - CONV) * 256 + threadIdx.x;
        const int T1 = 128 * 1152;
        const int T2 = 64 * 1152;
        if (idx < T1) {
            int n = idx / 1152, k = idx % 1152;
            float w = (k < 1024) ? W1[((size_t)(k >> 7) * 128 + (k & 127)) * 128 + n]
                                 : root1[(size_t)(k - 1024) * 128 + n];
            g_wb1[idx] = __float2half_rn(w);
        } else if (idx < T1 + T2) {
            int j = idx - T1;
            int n = j / 1152, k = j % 1152;
            float w = (k < 1024) ? W2[((size_t)(k >> 7) * 128 + (k & 127)) * 64 + n]
                                 : root2[(size_t)(k - 1024) * 64 + n];
            g_wb2[j] = __float2half_rn(w);
        }
    }
}

// ---------------- launch 2: offsets (warp-aggregated slot grab) ----------------
__global__ void off_kernel(int n8) {
    int i = blockIdx.x * blockDim.x + threadIdx.x;
    int lane = threadIdx.x & 31;
    int c = (i < n8) ? g_cnt[i] : 0;
    int incl = c;
    #pragma unroll
    for (int d = 1; d < 32; d <<= 1) {
        int t = __shfl_up_sync(0xffffffffu, incl, d);
        if (lane >= d) incl += t;
    }
    int tot = __shfl_sync(0xffffffffu, incl, 31);
    int base = 0;
    if (lane == 0) base = atomicAdd(&g_total, tot);
    base = __shfl_sync(0xffffffffu, base, 0);
    if (i < n8) {
        int start = base + incl - c;
        g_off8[i] = start;                 // fill cursor
        g_meta[i] = make_int2(start, c);   // immutable (start, count) for agg
    }
}

// ---------------- launch 3: fill (atomics on g_off8) + g_total reset ----------
__global__ void fill_kernel(const void* __restrict__ ei,
                            const void* __restrict__ et, int E) {
    bool idx64 = block_detect_idx64((const int*)ei);
    int e = blockIdx.x * blockDim.x + threadIdx.x;
    if (e == 0) g_total = 0;   // off already consumed it; reset for next replay
    if (e < E) {
        int src, dst, r;
        if (idx64) {
            src = (int)((const long long*)ei)[e];
            dst = (int)((const long long*)ei)[(long long)E + e];
            r   = (int)((const long long*)et)[e];
        } else {
            src = ((const int*)ei)[e];
            dst = ((const int*)ei)[E + e];
            r   = ((const int*)et)[e];
        }
        if ((unsigned)src < 50000u && (unsigned)dst < 50000u && (unsigned)r < 8u) {
            int pos = atomicAdd(&g_off8[dst * 8 + r], 1);
            g_epack[pos] = src;
        }
    }
}

// ---------------- aggregation: 8 lanes per (dst,rel) segment, fp32 acc --------
// fp16 row = 256 B = 16 uint4; lane l owns uint4[l] and uint4[l+8].
// Edge loop unrolled by 2 => 4 independent loads in flight per lane.
// c==0 segments exit immediately (xagg stays zero: static init + deterministic
// overwrite pattern across replays). Register cap lifts occupancy.
// SRC=0: g_xf -> g_xagg1. SRC=1: g_hf -> g_xagg2 (+ resets g_cnt for next replay).
template <int SRC>
__global__ void __launch_bounds__(256, 6)
agg_kernel(int n8) {
    int seg = (blockIdx.x * 256 + threadIdx.x) >> 3;
    int lane = threadIdx.x & 7;
    if (seg >= n8) return;
    int2 meta = g_meta[seg];
    int off = meta.x, c = meta.y;
    if (c == 0) return;                   // g_cnt[seg] already 0; xagg stays 0
    const __half* srcp = (SRC == 0) ? g_xf : g_hf;

    float acc[16];
    #pragma unroll
    for (int q = 0; q < 16; q++) acc[q] = 0.f;

    int j = 0;
    for (; j + 1 < c; j += 2) {
        int s0 = g_epack[off + j];
        int s1 = g_epack[off + j + 1];
        const uint4* r0 = (const uint4*)(srcp + (size_t)s0 * 128);
        const uint4* r1 = (const uint4*)(srcp + (size_t)s1 * 128);
        uint4 va = r0[lane], vb = r0[lane + 8];
        uint4 wa = r1[lane], wb = r1[lane + 8];
        const __half2* ha = (const __half2*)&va;
        const __half2* hb = (const __half2*)&vb;
        const __half2* ka = (const __half2*)&wa;
        const __half2* kb = (const __half2*)&wb;
        #pragma unroll
        for (int q = 0; q < 4; q++) {
            acc[2*q]      += __low2float(ha[q])  + __low2float(ka[q]);
            acc[2*q+1]    += __high2float(ha[q]) + __high2float(ka[q]);
            acc[8+2*q]    += __low2float(hb[q])  + __low2float(kb[q]);
            acc[8+2*q+1]  += __high2float(hb[q]) + __high2float(kb[q]);
        }
    }
    if (j < c) {
        int s0 = g_epack[off + j];
        const uint4* r0 = (const uint4*)(srcp + (size_t)s0 * 128);
        uint4 va = r0[lane], vb = r0[lane + 8];
        const __half2* ha = (const __half2*)&va;
        const __half2* hb = (const __half2*)&vb;
        #pragma unroll
        for (int q = 0; q < 4; q++) {
            acc[2*q]     += __low2float(ha[q]);
            acc[2*q+1]   += __high2float(ha[q]);
            acc[8+2*q]   += __low2float(hb[q]);
            acc[8+2*q+1] += __high2float(hb[q]);
        }
    }
    float w = 1.0f / (float)c;
    uint4 oa, ob;
    __half2* pa = (__half2*)&oa;
    __half2* pb = (__half2*)&ob;
    #pragma unroll
    for (int q = 0; q < 4; q++) {
        pa[q] = __floats2half2_rn(acc[2*q] * w, acc[2*q+1] * w);
        pb[q] = __floats2half2_rn(acc[8+2*q] * w, acc[8+2*q+1] * w);
    }
    __half* dstp = (SRC == 0) ? g_xagg1 : g_xagg2;
    ((uint4*)(dstp + (size_t)seg * 128))[lane] = oa;
    ((uint4*)(dstp + (size_t)seg * 128))[lane + 8] = ob;

    if (SRC == 1 && lane == 0) g_cnt[seg] = 0;   // restore for next replay
}

// ---------------- GEMM: out[m,:] = A[m,0:1152] @ Wstack + bias ----------------
// Single fp16 product both layers. L1 epilogue: relu -> g_hf; L2: sigmoid -> out.
template <int FOUT, int LAYER>
__global__ void __launch_bounds__(256)
mm_kernel(const float* __restrict__ bias, float* __restrict__ outExt, int M) {
    constexpr int WN = (FOUT == 128) ? 64 : 32;
    constexpr int NFR = WN / 8;
    constexpr int TB = 128;                 // bytes per smem row (64 fp16)
    constexpr int ABYT = 128 * TB;          // 16 KB
    constexpr int BBYT = FOUT * TB;         // 16 or 8 KB
    constexpr int STAGE = ABYT + BBYT;
    constexpr int NCHUNK = 18;

    extern __shared__ char smem[];
    const unsigned sbase = smem_u32(smem);

    const __half* wb = (LAYER == 1) ? g_wb1 : g_wb2;

    const int tid = threadIdx.x;
    const int wid = tid >> 5, lane = tid & 31;
    const int wm = wid & 3, wn = wid >> 2;
    const int g = lane >> 2, t = lane & 3;
    const int m0 = blockIdx.x * 128;

    float acc[2][NFR][4];
    #pragma unroll
    for (int mi = 0; mi < 2; mi++)
        #pragma unroll
        for (int ni = 0; ni < NFR; ni++)
            #pragma unroll
            for (int q = 0; q < 4; q++) acc[mi][ni][q] = 0.f;

    auto load_chunk = [&](int c, int s) {
        const unsigned a0 = sbase + s * STAGE;
        const unsigned b0 = a0 + ABYT;
        #pragma unroll
        for (int i = 0; i < 4; i++) {
            int idx = tid + i * 256;
            int row = idx >> 3, t16 = idx & 7;
            const __half* s0;
            size_t go;
            if (c < 16) {
                s0 = (LAYER == 1) ? g_xagg1 : g_xagg2;
                go = (size_t)(m0 + row) * 1024 + c * 64 + t16 * 8;
            } else {
                s0 = (LAYER == 1) ? g_xf : g_hf;
                go = (size_t)(m0 + row) * 128 + (c - 16) * 64 + t16 * 8;
            }
            unsigned d = a0 + row * TB + ((t16 * 16) ^ ((row & 7) * 16));
            cp16(d, s0 + go);
        }
        #pragma unroll
        for (int i = 0; i < FOUT / 32; i++) {
            int idx = tid + i * 256;
            int row = idx >> 3, t16 = idx & 7;
            size_t go = (size_t)row * 1152 + c * 64 + t16 * 8;
            unsigned d = b0 + row * TB + ((t16 * 16) ^ ((row & 7) * 16));
            cp16(d, wb + go);
        }
    };

    load_chunk(0, 0);
    CP_COMMIT();

    #pragma unroll 1
    for (int c = 0; c < NCHUNK; c++) {
        if (c < NCHUNK - 1) {
            load_chunk(c + 1, (c + 1) & 1);
            CP_COMMIT();
            CP_WAIT(1);
        } else {
            CP_WAIT(0);
        }
        __syncthreads();

        const int s = c & 1;
        const unsigned sA = sbase + s * STAGE;
        const unsigned sB = sA + ABYT;

        #pragma unroll
        for (int ks = 0; ks < 4; ks++) {
            const int kb = ks * 32 + t * 4;
            unsigned ah[2][4], bh[NFR][2];
            #pragma unroll
            for (int mi = 0; mi < 2; mi++) {
                int r0 = wm * 32 + mi * 16 + g;
                int r1 = r0 + 8;
                unsigned o00 = r0 * TB + (kb ^ ((r0 & 7) * 16));
                unsigned o10 = r1 * TB + (kb ^ ((r1 & 7) * 16));
                unsigned o01 = r0 * TB + ((kb + 16) ^ ((r0 & 7) * 16));
                unsigned o11 = r1 * TB + ((kb + 16) ^ ((r1 & 7) * 16));
                ah[mi][0] = lds32(sA + o00); ah[mi][1] = lds32(sA + o10);
                ah[mi][2] = lds32(sA + o01); ah[mi][3] = lds32(sA + o11);
            }
            #pragma unroll
            for (int ni = 0; ni < NFR; ni++) {
                int nr = wn * WN + ni * 8 + g;
                unsigned o0 = nr * TB + (kb ^ ((nr & 7) * 16));
                unsigned o1 = nr * TB + ((kb + 16) ^ ((nr & 7) * 16));
                bh[ni][0] = lds32(sB + o0); bh[ni][1] = lds32(sB + o1);
            }
            #pragma unroll
            for (int mi = 0; mi < 2; mi++)
                #pragma unroll
                for (int ni = 0; ni < NFR; ni++)
                    mma_fp16(acc[mi][ni], ah[mi], bh[ni]);
        }
        __syncthreads();
    }

    // -------- epilogue --------
    #pragma unroll
    for (int mi = 0; mi < 2; mi++) {
        int row0 = m0 + wm * 32 + mi * 16 + g;
        #pragma unroll
        for (int ni = 0; ni < NFR; ni++) {
            int col = wn * WN + ni * 8 + 2 * t;
            float b0 = bias[col], b1 = bias[col + 1];
            float v[4] = {acc[mi][ni][0] + b0, acc[mi][ni][1] + b1,
                          acc[mi][ni][2] + b0, acc[mi][ni][3] + b1};
            if (LAYER == 1) {
                #pragma unroll
                for (int q = 0; q < 4; q++) v[q] = fmaxf(v[q], 0.f);
                if (row0 < M)
                    *(__half2*)(g_hf + (size_t)row0 * 128 + col) =
                        __floats2half2_rn(v[0], v[1]);
                if (row0 + 8 < M)
                    *(__half2*)(g_hf + (size_t)(row0 + 8) * 128 + col) =
                        __floats2half2_rn(v[2], v[3]);
            } else {
                #pragma unroll
                for (int q = 0; q < 4; q++) v[q] = 1.0f / (1.0f + expf(-v[q]));
                if (row0 < M)
                    *(float2*)(outExt + (size_t)row0 * FOUT + col) = make_float2(v[0], v[1]);
                if (row0 + 8 < M)
                    *(float2*)(outExt + (size_t)(row0 + 8) * FOUT + col) = make_float2(v[2], v[3]);
            }
        }
    }
}

// ---------------- launch ----------------
extern "C" void kernel_launch(void* const* d_in, const int* in_sizes, int n_in,
                              void* d_out, int out_size) {
    const float* x     = (const float*)d_in[0];
    const void*  ei    = d_in[1];
    const void*  et    = d_in[2];
    const float* W1    = (const float*)d_in[3];
    const float* root1 = (const float*)d_in[4];
    const float* b1    = (const float*)d_in[5];
    const float* W2    = (const float*)d_in[6];
    const float* root2 = (const float*)d_in[7];
    const float* b2    = (const float*)d_in[8];
    float* out = (float*)d_out;

    const int M = in_sizes[0] / 128;   // 50000
    const int E = in_sizes[2];         // 500000
    const int n8 = M * 8;

    const int SM1 = 2 * (16384 + 16384);  // 64 KB
    const int SM2 = 2 * (16384 + 8192);   // 48 KB
    static int configured = 0;
    if (!configured) {
        cudaFuncSetAttribute((const void*)&mm_kernel<128, 1>,
                             cudaFuncAttributeMaxDynamicSharedMemorySize, SM1);
        cudaFuncSetAttribute((const void*)&mm_kernel<64, 2>,
                             cudaFuncAttributeMaxDynamicSharedMemorySize, SM2);
        configured = 1;
    }

    // ---- launch 1: count + conv1 + W pack ----
    const int CNT  = (E + 255) / 256;
    const int CONV = (M * 32 + 255) / 256;
    const int PACK = (128 * 1152 + 64 * 1152 + 255) / 256;
    stage1_kernel<<<CNT + CONV + PACK, 256>>>(ei, et, x, W1, root1, W2, root2, E, M);

    // ---- CSR offsets + fill ----
    off_kernel<<<(n8 + 255) / 256, 256>>>(n8);
    fill_kernel<<<(E + 255) / 256, 256>>>(ei, et, E);

    const int mblocks = (M + 127) / 128;
    const int ablocks = (n8 * 8 + 255) / 256;   // 8 lanes per segment

    // ---- layer 1 ----
    agg_kernel<0><<<ablocks, 256>>>(n8);
    mm_kernel<128, 1><<<mblocks, 256, SM1>>>(b1, nullptr, M);

    // ---- layer 2 ----
    agg_kernel<1><<<ablocks, 256>>>(n8);
    mm_kernel<64, 2><<<mblocks, 256, SM2>>>(b2, out, M);
}

// round 15
// speedup vs baseline: 1.0963x; 1.0963x over previous
#include <cuda_runtime.h>
#include <cuda_fp16.h>
#include <math.h>

#define NMAX 50048   // 391*128 padded so GEMM tile reads stay in-bounds
#define EMAX 500000

// ---------------- static scratch (zero-initialized at load; every replay
// restores g_cnt=0 / g_total=0 at its end, so graph replays are deterministic) --
__device__ __half g_xagg1[(size_t)NMAX * 1024];  // L1 per-(dst,rel) mean, fp16
__device__ __half g_xagg2[(size_t)NMAX * 1024];  // L2 per-(dst,rel) mean, fp16
__device__ __half g_xf[(size_t)NMAX * 128];      // L1 root input, fp16
__device__ __half g_hf[(size_t)NMAX * 128];      // relu(h), fp16
__device__ __half g_wb1[128 * 1152];             // L1 stacked W, fp16
__device__ __half g_wb2[64 * 1152];              // L2 stacked W, fp16
__device__ int   g_cnt[NMAX * 8];
__device__ int   g_off8[NMAX * 8];               // fill cursor (start -> end)
__device__ int2  g_meta[NMAX * 8];               // (start, count) — one 8B load
__device__ int   g_epack[EMAX];
__device__ int   g_total;

// ---------------- helpers ----------------
__device__ __forceinline__ unsigned smem_u32(const void* p) {
    unsigned a;
    asm("{ .reg .u64 t; cvta.to.shared.u64 t, %1; cvt.u32.u64 %0, t; }"
        : "=r"(a) : "l"(p));
    return a;
}
__device__ __forceinline__ unsigned lds32(unsigned a) {
    unsigned v;
    asm volatile("ld.shared.b32 %0, [%1];" : "=r"(v) : "r"(a));
    return v;
}
__device__ __forceinline__ void cp16(unsigned dst, const void* src) {
    asm volatile("cp.async.cg.shared.global [%0], [%1], 16;"
                 :: "r"(dst), "l"(src) : "memory");
}
#define CP_COMMIT() asm volatile("cp.async.commit_group;" ::: "memory")
#define CP_WAIT(n)  asm volatile("cp.async.wait_group %0;" :: "n"(n) : "memory")

__device__ __forceinline__ void mma_fp16(float* c, const unsigned* a, const unsigned* b) {
    asm volatile("mma.sync.aligned.m16n8k16.row.col.f32.f16.f16.f32 "
                 "{%0,%1,%2,%3}, {%4,%5,%6,%7}, {%8,%9}, {%0,%1,%2,%3};"
                 : "+f"(c[0]), "+f"(c[1]), "+f"(c[2]), "+f"(c[3])
                 : "r"(a[0]), "r"(a[1]), "r"(a[2]), "r"(a[3]),
                   "r"(b[0]), "r"(b[1]));
}

// block-local index dtype detect: int64 (LE) => odd 32-bit words all zero over
// 256 samples; int32 => some nonzero. Values are node ids < 50000.
__device__ __forceinline__ bool block_detect_idx64(const int* ei32) {
    __shared__ int any;
    if (threadIdx.x == 0) any = 0;
    __syncthreads();
    if (threadIdx.x < 256 && ei32[2 * threadIdx.x + 1] != 0) atomicOr(&any, 1);
    __syncthreads();
    return any == 0;
}

// ---------------- launch 1: count + conv1 + W pack (independent block ranges) --
__global__ void __launch_bounds__(256)
stage1_kernel(const void* __restrict__ ei, const void* __restrict__ et,
              const float* __restrict__ x,
              const float* __restrict__ W1, const float* __restrict__ root1,
              const float* __restrict__ W2, const float* __restrict__ root2,
              int E, int M) {
    const int CNT  = (E + 255) / 256;
    const int CONV = (M * 32 + 255) / 256;
    int b = blockIdx.x;

    if (b < CNT) {
        bool idx64 = block_detect_idx64((const int*)ei);
        int e = b * 256 + threadIdx.x;
        if (e < E) {
            int dst, r;
            if (idx64) {
                dst = (int)((const long long*)ei)[(long long)E + e];
                r   = (int)((const long long*)et)[e];
            } else {
                dst = ((const int*)ei)[E + e];
                r   = ((const int*)et)[e];
            }
            if ((unsigned)dst < 50000u && (unsigned)r < 8u)
                atomicAdd(&g_cnt[dst * 8 + r], 1);
        }
    } else if (b < CNT + CONV) {
        int i = (b - CNT) * 256 + threadIdx.x;
        if (i >= M * 32) return;
        float4 v = ((const float4*)x)[i];
        __half2* d = (__half2*)(g_xf + (size_t)i * 4);
        d[0] = __floats2half2_rn(v.x, v.y);
        d[1] = __floats2half2_rn(v.z, v.w);
    } else {
        int idx = (b - CNT - CONV) * 256 + threadIdx.x;
        const int T1 = 128 * 1152;
        const int T2 = 64 * 1152;
        if (idx < T1) {
            int n = idx / 1152, k = idx % 1152;
            float w = (k < 1024) ? W1[((size_t)(k >> 7) * 128 + (k & 127)) * 128 + n]
                                 : root1[(size_t)(k - 1024) * 128 + n];
            g_wb1[idx] = __float2half_rn(w);
        } else if (idx < T1 + T2) {
            int j = idx - T1;
            int n = j / 1152, k = j % 1152;
            float w = (k < 1024) ? W2[((size_t)(k >> 7) * 128 + (k & 127)) * 64 + n]
                                 : root2[(size_t)(k - 1024) * 64 + n];
            g_wb2[j] = __float2half_rn(w);
        }
    }
}

// ---------------- launch 2: offsets (warp-aggregated slot grab) ----------------
__global__ void off_kernel(int n8) {
    int i = blockIdx.x * blockDim.x + threadIdx.x;
    int lane = threadIdx.x & 31;
    int c = (i < n8) ? g_cnt[i] : 0;
    int incl = c;
    #pragma unroll
    for (int d = 1; d < 32; d <<= 1) {
        int t = __shfl_up_sync(0xffffffffu, incl, d);
        if (lane >= d) incl += t;
    }
    int tot = __shfl_sync(0xffffffffu, incl, 31);
    int base = 0;
    if (lane == 0) base = atomicAdd(&g_total, tot);
    base = __shfl_sync(0xffffffffu, base, 0);
    if (i < n8) {
        int start = base + incl - c;
        g_off8[i] = start;                 // fill cursor
        g_meta[i] = make_int2(start, c);   // immutable (start, count) for agg
    }
}

// ---------------- launch 3: fill (atomics on g_off8) + g_total reset ----------
__global__ void fill_kernel(const void* __restrict__ ei,
                            const void* __restrict__ et, int E) {
    bool idx64 = block_detect_idx64((const int*)ei);
    int e = blockIdx.x * blockDim.x + threadIdx.x;
    if (e == 0) g_total = 0;   // off already consumed it; reset for next replay
    if (e < E) {
        int src, dst, r;
        if (idx64) {
            src = (int)((const long long*)ei)[e];
            dst = (int)((const long long*)ei)[(long long)E + e];
            r   = (int)((const long long*)et)[e];
        } else {
            src = ((const int*)ei)[e];
            dst = ((const int*)ei)[E + e];
            r   = ((const int*)et)[e];
        }
        if ((unsigned)src < 50000u && (unsigned)dst < 50000u && (unsigned)r < 8u) {
            int pos = atomicAdd(&g_off8[dst * 8 + r], 1);
            g_epack[pos] = src;
        }
    }
}

// ---------------- aggregation: 8 lanes per (dst,rel) segment, fp32 acc --------
// fp16 row = 256 B = 16 uint4; lane l owns uint4[l] and uint4[l+8].
// Edge loop unrolled by 2 => 4 independent loads in flight per lane.
// R12 configuration exactly (no reg cap, fp32 acc); the only addition is a
// PREDICATED skip for c==0 segments (no early return, no extra live state):
// they issue no loads and no stores — xagg rows stay zero (static init,
// deterministic across replays since those segments are never written).
// SRC=0: g_xf -> g_xagg1. SRC=1: g_hf -> g_xagg2 (+ resets g_cnt for replay).
template <int SRC>
__global__ void __launch_bounds__(256)
agg_kernel(int n8) {
    int seg = (blockIdx.x * 256 + threadIdx.x) >> 3;
    int lane = threadIdx.x & 7;
    if (seg >= n8) return;
    int2 meta = g_meta[seg];
    int off = meta.x, c = meta.y;
    const __half* srcp = (SRC == 0) ? g_xf : g_hf;

    float acc[16];
    #pragma unroll
    for (int q = 0; q < 16; q++) acc[q] = 0.f;

    int j = 0;
    for (; j + 1 < c; j += 2) {
        int s0 = g_epack[off + j];
        int s1 = g_epack[off + j + 1];
        const uint4* r0 = (const uint4*)(srcp + (size_t)s0 * 128);
        const uint4* r1 = (const uint4*)(srcp + (size_t)s1 * 128);
        uint4 va = r0[lane], vb = r0[lane + 8];
        uint4 wa = r1[lane], wb = r1[lane + 8];
        const __half2* ha = (const __half2*)&va;
        const __half2* hb = (const __half2*)&vb;
        const __half2* ka = (const __half2*)&wa;
        const __half2* kb = (const __half2*)&wb;
        #pragma unroll
        for (int q = 0; q < 4; q++) {
            acc[2*q]      += __low2float(ha[q])  + __low2float(ka[q]);
            acc[2*q+1]    += __high2float(ha[q]) + __high2float(ka[q]);
            acc[8+2*q]    += __low2float(hb[q])  + __low2float(kb[q]);
            acc[8+2*q+1]  += __high2float(hb[q]) + __high2float(kb[q]);
        }
    }
    if (j < c) {
        int s0 = g_epack[off + j];
        const uint4* r0 = (const uint4*)(srcp + (size_t)s0 * 128);
        uint4 va = r0[lane], vb = r0[lane + 8];
        const __half2* ha = (const __half2*)&va;
        const __half2* hb = (const __half2*)&vb;
        #pragma unroll
        for (int q = 0; q < 4; q++) {
            acc[2*q]     += __low2float(ha[q]);
            acc[2*q+1]   += __high2float(ha[q]);
            acc[8+2*q]   += __low2float(hb[q]);
            acc[8+2*q+1] += __high2float(hb[q]);
        }
    }

    if (c > 0) {                           // predicated skip: no store for c==0
        float w = 1.0f / (float)c;
        uint4 oa, ob;
        __half2* pa = (__half2*)&oa;
        __half2* pb = (__half2*)&ob;
        #pragma unroll
        for (int q = 0; q < 4; q++) {
            pa[q] = __floats2half2_rn(acc[2*q] * w, acc[2*q+1] * w);
            pb[q] = __floats2half2_rn(acc[8+2*q] * w, acc[8+2*q+1] * w);
        }
        __half* dstp = (SRC == 0) ? g_xagg1 : g_xagg2;
        ((uint4*)(dstp + (size_t)seg * 128))[lane] = oa;
        ((uint4*)(dstp + (size_t)seg * 128))[lane + 8] = ob;
    }

    if (SRC == 1 && lane == 0 && c > 0) g_cnt[seg] = 0;   // restore for replay
}

// ---------------- GEMM: out[m,:] = A[m,0:1152] @ Wstack + bias ----------------
// Single fp16 product both layers. L1 epilogue: relu -> g_hf; L2: sigmoid -> out.
template <int FOUT, int LAYER>
__global__ void __launch_bounds__(256)
mm_kernel(const float* __restrict__ bias, float* __restrict__ outExt, int M) {
    constexpr int WN = (FOUT == 128) ? 64 : 32;
    constexpr int NFR = WN / 8;
    constexpr int TB = 128;                 // bytes per smem row (64 fp16)
    constexpr int ABYT = 128 * TB;          // 16 KB
    constexpr int BBYT = FOUT * TB;         // 16 or 8 KB
    constexpr int STAGE = ABYT + BBYT;
    constexpr int NCHUNK = 18;

    extern __shared__ char smem[];
    const unsigned sbase = smem_u32(smem);

    const __half* wb = (LAYER == 1) ? g_wb1 : g_wb2;

    const int tid = threadIdx.x;
    const int wid = tid >> 5, lane = tid & 31;
    const int wm = wid & 3, wn = wid >> 2;
    const int g = lane >> 2, t = lane & 3;
    const int m0 = blockIdx.x * 128;

    float acc[2][NFR][4];
    #pragma unroll
    for (int mi = 0; mi < 2; mi++)
        #pragma unroll
        for (int ni = 0; ni < NFR; ni++)
            #pragma unroll
            for (int q = 0; q < 4; q++) acc[mi][ni][q] = 0.f;

    auto load_chunk = [&](int c, int s) {
        const unsigned a0 = sbase + s * STAGE;
        const unsigned b0 = a0 + ABYT;
        #pragma unroll
        for (int i = 0; i < 4; i++) {
            int idx = tid + i * 256;
            int row = idx >> 3, t16 = idx & 7;
            const __half* s0;
            size_t go;
            if (c < 16) {
                s0 = (LAYER == 1) ? g_xagg1 : g_xagg2;
                go = (size_t)(m0 + row) * 1024 + c * 64 + t16 * 8;
            } else {
                s0 = (LAYER == 1) ? g_xf : g_hf;
                go = (size_t)(m0 + row) * 128 + (c - 16) * 64 + t16 * 8;
            }
            unsigned d = a0 + row * TB + ((t16 * 16) ^ ((row & 7) * 16));
            cp16(d, s0 + go);
        }
        #pragma unroll
        for (int i = 0; i < FOUT / 32; i++) {
            int idx = tid + i * 256;
            int row = idx >> 3, t16 = idx & 7;
            size_t go = (size_t)row * 1152 + c * 64 + t16 * 8;
            unsigned d = b0 + row * TB + ((t16 * 16) ^ ((row & 7) * 16));
            cp16(d, wb + go);
        }
    };

    load_chunk(0, 0);
    CP_COMMIT();

    #pragma unroll 1
    for (int c = 0; c < NCHUNK; c++) {
        if (c < NCHUNK - 1) {
            load_chunk(c + 1, (c + 1) & 1);
            CP_COMMIT();
            CP_WAIT(1);
        } else {
            CP_WAIT(0);
        }
        __syncthreads();

        const int s = c & 1;
        const unsigned sA = sbase + s * STAGE;
        const unsigned sB = sA + ABYT;

        #pragma unroll
        for (int ks = 0; ks < 4; ks++) {
            const int kb = ks * 32 + t * 4;
            unsigned ah[2][4], bh[NFR][2];
            #pragma unroll
            for (int mi = 0; mi < 2; mi++) {
                int r0 = wm * 32 + mi * 16 + g;
                int r1 = r0 + 8;
                unsigned o00 = r0 * TB + (kb ^ ((r0 & 7) * 16));
                unsigned o10 = r1 * TB + (kb ^ ((r1 & 7) * 16));
                unsigned o01 = r0 * TB + ((kb + 16) ^ ((r0 & 7) * 16));
                unsigned o11 = r1 * TB + ((kb + 16) ^ ((r1 & 7) * 16));
                ah[mi][0] = lds32(sA + o00); ah[mi][1] = lds32(sA + o10);
                ah[mi][2] = lds32(sA + o01); ah[mi][3] = lds32(sA + o11);
            }
            #pragma unroll
            for (int ni = 0; ni < NFR; ni++) {
                int nr = wn * WN + ni * 8 + g;
                unsigned o0 = nr * TB + (kb ^ ((nr & 7) * 16));
                unsigned o1 = nr * TB + ((kb + 16) ^ ((nr & 7) * 16));
                bh[ni][0] = lds32(sB + o0); bh[ni][1] = lds32(sB + o1);
            }
            #pragma unroll
            for (int mi = 0; mi < 2; mi++)
                #pragma unroll
                for (int ni = 0; ni < NFR; ni++)
                    mma_fp16(acc[mi][ni], ah[mi], bh[ni]);
        }
        __syncthreads();
    }

    // -------- epilogue --------
    #pragma unroll
    for (int mi = 0; mi < 2; mi++) {
        int row0 = m0 + wm * 32 + mi * 16 + g;
        #pragma unroll
        for (int ni = 0; ni < NFR; ni++) {
            int col = wn * WN + ni * 8 + 2 * t;
            float b0 = bias[col], b1 = bias[col + 1];
            float v[4] = {acc[mi][ni][0] + b0, acc[mi][ni][1] + b1,
                          acc[mi][ni][2] + b0, acc[mi][ni][3] + b1};
            if (LAYER == 1) {
                #pragma unroll
                for (int q = 0; q < 4; q++) v[q] = fmaxf(v[q], 0.f);
                if (row0 < M)
                    *(__half2*)(g_hf + (size_t)row0 * 128 + col) =
                        __floats2half2_rn(v[0], v[1]);
                if (row0 + 8 < M)
                    *(__half2*)(g_hf + (size_t)(row0 + 8) * 128 + col) =
                        __floats2half2_rn(v[2], v[3]);
            } else {
                #pragma unroll
                for (int q = 0; q < 4; q++) v[q] = 1.0f / (1.0f + expf(-v[q]));
                if (row0 < M)
                    *(float2*)(outExt + (size_t)row0 * FOUT + col) = make_float2(v[0], v[1]);
                if (row0 + 8 < M)
                    *(float2*)(outExt + (size_t)(row0 + 8) * FOUT + col) = make_float2(v[2], v[3]);
            }
        }
    }
}

// ---------------- launch ----------------
extern "C" void kernel_launch(void* const* d_in, const int* in_sizes, int n_in,
                              void* d_out, int out_size) {
    const float* x     = (const float*)d_in[0];
    const void*  ei    = d_in[1];
    const void*  et    = d_in[2];
    const float* W1    = (const float*)d_in[3];
    const float* root1 = (const float*)d_in[4];
    const float* b1    = (const float*)d_in[5];
    const float* W2    = (const float*)d_in[6];
    const float* root2 = (const float*)d_in[7];
    const float* b2    = (const float*)d_in[8];
    float* out = (float*)d_out;

    const int M = in_sizes[0] / 128;   // 50000
    const int E = in_sizes[2];         // 500000
    const int n8 = M * 8;

    const int SM1 = 2 * (16384 + 16384);  // 64 KB
    const int SM2 = 2 * (16384 + 8192);   // 48 KB
    static int configured = 0;
    if (!configured) {
        cudaFuncSetAttribute((const void*)&mm_kernel<128, 1>,
                             cudaFuncAttributeMaxDynamicSharedMemorySize, SM1);
        cudaFuncSetAttribute((const void*)&mm_kernel<64, 2>,
                             cudaFuncAttributeMaxDynamicSharedMemorySize, SM2);
        configured = 1;
    }

    // ---- launch 1: count + conv1 + W pack ----
    const int CNT  = (E + 255) / 256;
    const int CONV = (M * 32 + 255) / 256;
    const int PACK = (128 * 1152 + 64 * 1152 + 255) / 256;
    stage1_kernel<<<CNT + CONV + PACK, 256>>>(ei, et, x, W1, root1, W2, root2, E, M);

    // ---- CSR offsets + fill ----
    off_kernel<<<(n8 + 255) / 256, 256>>>(n8);
    fill_kernel<<<(E + 255) / 256, 256>>>(ei, et, E);

    const int mblocks = (M + 127) / 128;
    const int ablocks = (n8 * 8 + 255) / 256;   // 8 lanes per segment

    // ---- layer 1 ----
    agg_kernel<0><<<ablocks, 256>>>(n8);
    mm_kernel<128, 1><<<mblocks, 256, SM1>>>(b1, nullptr, M);

    // ---- layer 2 ----
    agg_kernel<1><<<ablocks, 256>>>(n8);
    mm_kernel<64, 2><<<mblocks, 256, SM2>>>(b2, out, M);
}

// round 16
// speedup vs baseline: 1.1406x; 1.0405x over previous
#include <cuda_runtime.h>
#include <cuda_fp16.h>
#include <math.h>

#define NMAX 50048   // 391*128 padded so GEMM tile reads stay in-bounds
#define EMAX 500000

// ---------------- static scratch (zero-initialized at load; every replay
// restores g_cnt=0 / g_total=0 at its end, so graph replays are deterministic) --
__device__ __half g_xagg1[(size_t)NMAX * 1024];  // L1 per-(dst,rel) mean, fp16
__device__ __half g_xagg2[(size_t)NMAX * 1024];  // L2 per-(dst,rel) mean, fp16
__device__ __half g_xf[(size_t)NMAX * 128];      // L1 root input, fp16
__device__ __half g_hf[(size_t)NMAX * 128];      // relu(h), fp16
__device__ __half g_wb1[128 * 1152];             // L1 stacked W, fp16
__device__ __half g_wb2[64 * 1152];              // L2 stacked W, fp16
__device__ int   g_cnt[NMAX * 8];
__device__ int   g_off8[NMAX * 8];               // fill cursor (start -> end)
__device__ int2  g_meta[NMAX * 8];               // (start, count) — one 8B load
__device__ int   g_epack[EMAX];
__device__ int   g_total;

// ---------------- helpers ----------------
__device__ __forceinline__ unsigned smem_u32(const void* p) {
    unsigned a;
    asm("{ .reg .u64 t; cvta.to.shared.u64 t, %1; cvt.u32.u64 %0, t; }"
        : "=r"(a) : "l"(p));
    return a;
}
__device__ __forceinline__ unsigned lds32(unsigned a) {
    unsigned v;
    asm volatile("ld.shared.b32 %0, [%1];" : "=r"(v) : "r"(a));
    return v;
}
__device__ __forceinline__ void cp16(unsigned dst, const void* src) {
    asm volatile("cp.async.cg.shared.global [%0], [%1], 16;"
                 :: "r"(dst), "l"(src) : "memory");
}
#define CP_COMMIT() asm volatile("cp.async.commit_group;" ::: "memory")
#define CP_WAIT(n)  asm volatile("cp.async.wait_group %0;" :: "n"(n) : "memory")

__device__ __forceinline__ void mma_fp16(float* c, const unsigned* a, const unsigned* b) {
    asm volatile("mma.sync.aligned.m16n8k16.row.col.f32.f16.f16.f32 "
                 "{%0,%1,%2,%3}, {%4,%5,%6,%7}, {%8,%9}, {%0,%1,%2,%3};"
                 : "+f"(c[0]), "+f"(c[1]), "+f"(c[2]), "+f"(c[3])
                 : "r"(a[0]), "r"(a[1]), "r"(a[2]), "r"(a[3]),
                   "r"(b[0]), "r"(b[1]));
}

// block-local index dtype detect: int64 (LE) => odd 32-bit words all zero over
// 256 samples; int32 => some nonzero. Values are node ids < 50000.
__device__ __forceinline__ bool block_detect_idx64(const int* ei32) {
    __shared__ int any;
    if (threadIdx.x == 0) any = 0;
    __syncthreads();
    if (threadIdx.x < 256 && ei32[2 * threadIdx.x + 1] != 0) atomicOr(&any, 1);
    __syncthreads();
    return any == 0;
}

// ---------------- launch 1: count + conv1 + W pack (independent block ranges) --
__global__ void __launch_bounds__(256)
stage1_kernel(const void* __restrict__ ei, const void* __restrict__ et,
              const float* __restrict__ x,
              const float* __restrict__ W1, const float* __restrict__ root1,
              const float* __restrict__ W2, const float* __restrict__ root2,
              int E, int M) {
    const int CNT  = (E + 255) / 256;
    const int CONV = (M * 32 + 255) / 256;
    int b = blockIdx.x;

    if (b < CNT) {
        bool idx64 = block_detect_idx64((const int*)ei);
        int e = b * 256 + threadIdx.x;
        if (e < E) {
            int dst, r;
            if (idx64) {
                dst = (int)((const long long*)ei)[(long long)E + e];
                r   = (int)((const long long*)et)[e];
            } else {
                dst = ((const int*)ei)[E + e];
                r   = ((const int*)et)[e];
            }
            if ((unsigned)dst < 50000u && (unsigned)r < 8u)
                atomicAdd(&g_cnt[dst * 8 + r], 1);
        }
    } else if (b < CNT + CONV) {
        int i = (b - CNT) * 256 + threadIdx.x;
        if (i >= M * 32) return;
        float4 v = ((const float4*)x)[i];
        __half2* d = (__half2*)(g_xf + (size_t)i * 4);
        d[0] = __floats2half2_rn(v.x, v.y);
        d[1] = __floats2half2_rn(v.z, v.w);
    } else {
        int idx = (b - CNT - CONV) * 256 + threadIdx.x;
        const int T1 = 128 * 1152;
        const int T2 = 64 * 1152;
        if (idx < T1) {
            int n = idx / 1152, k = idx % 1152;
            float w = (k < 1024) ? W1[((size_t)(k >> 7) * 128 + (k & 127)) * 128 + n]
                                 : root1[(size_t)(k - 1024) * 128 + n];
            g_wb1[idx] = __float2half_rn(w);
        } else if (idx < T1 + T2) {
            int j = idx - T1;
            int n = j / 1152, k = j % 1152;
            float w = (k < 1024) ? W2[((size_t)(k >> 7) * 128 + (k & 127)) * 64 + n]
                                 : root2[(size_t)(k - 1024) * 64 + n];
            g_wb2[j] = __float2half_rn(w);
        }
    }
}

// ---------------- launch 2: offsets — 4 segments per thread (int4) ------------
__global__ void off_kernel(int n4) {   // n4 = n8 / 4
    int i = blockIdx.x * blockDim.x + threadIdx.x;
    int lane = threadIdx.x & 31;
    int4 c4 = make_int4(0, 0, 0, 0);
    if (i < n4) c4 = ((const int4*)g_cnt)[i];
    int s = c4.x + c4.y + c4.z + c4.w;
    int incl = s;
    #pragma unroll
    for (int d = 1; d < 32; d <<= 1) {
        int t = __shfl_up_sync(0xffffffffu, incl, d);
        if (lane >= d) incl += t;
    }
    int tot = __shfl_sync(0xffffffffu, incl, 31);
    int base = 0;
    if (lane == 0) base = atomicAdd(&g_total, tot);
    base = __shfl_sync(0xffffffffu, base, 0);
    if (i < n4) {
        int o0 = base + incl - s;
        int o1 = o0 + c4.x;
        int o2 = o1 + c4.y;
        int o3 = o2 + c4.z;
        ((int4*)g_off8)[i] = make_int4(o0, o1, o2, o3);        // fill cursors
        int4* mp = (int4*)&g_meta[i * 4];                       // (start,count)x4
        mp[0] = make_int4(o0, c4.x, o1, c4.y);
        mp[1] = make_int4(o2, c4.z, o3, c4.w);
    }
}

// ---------------- launch 3: fill (atomics on g_off8) + g_total reset ----------
__global__ void fill_kernel(const void* __restrict__ ei,
                            const void* __restrict__ et, int E) {
    bool idx64 = block_detect_idx64((const int*)ei);
    int e = blockIdx.x * blockDim.x + threadIdx.x;
    if (e == 0) g_total = 0;   // off already consumed it; reset for next replay
    if (e < E) {
        int src, dst, r;
        if (idx64) {
            src = (int)((const long long*)ei)[e];
            dst = (int)((const long long*)ei)[(long long)E + e];
            r   = (int)((const long long*)et)[e];
        } else {
            src = ((const int*)ei)[e];
            dst = ((const int*)ei)[E + e];
            r   = ((const int*)et)[e];
        }
        if ((unsigned)src < 50000u && (unsigned)dst < 50000u && (unsigned)r < 8u) {
            int pos = atomicAdd(&g_off8[dst * 8 + r], 1);
            g_epack[pos] = src;
        }
    }
}

// ---------------- aggregation: 8 lanes per (dst,rel) segment, fp32 acc --------
// fp16 row = 256 B = 16 uint4; lane l owns uint4[l] and uint4[l+8].
// Unroll-2 body now pre-sums the two edges with HADD2 (8 ops, in-place on
// already-live load registers) before the fp32 cvt+add (16 elements) —
// 64 -> 40 F-ops per 2 edges, accumulator & liveness unchanged vs R15.
// c==0 segments skip loads and stores (xagg rows stay zero; static init,
// deterministic across replays since those segments are never written).
// SRC=0: g_xf -> g_xagg1. SRC=1: g_hf -> g_xagg2 (+ resets g_cnt for replay).
template <int SRC>
__global__ void __launch_bounds__(256)
agg_kernel(int n8) {
    int seg = (blockIdx.x * 256 + threadIdx.x) >> 3;
    int lane = threadIdx.x & 7;
    if (seg >= n8) return;
    int2 meta = g_meta[seg];
    int off = meta.x, c = meta.y;
    const __half* srcp = (SRC == 0) ? g_xf : g_hf;

    float acc[16];
    #pragma unroll
    for (int q = 0; q < 16; q++) acc[q] = 0.f;

    int j = 0;
    for (; j + 1 < c; j += 2) {
        int s0 = g_epack[off + j];
        int s1 = g_epack[off + j + 1];
        const uint4* r0 = (const uint4*)(srcp + (size_t)s0 * 128);
        const uint4* r1 = (const uint4*)(srcp + (size_t)s1 * 128);
        uint4 va = r0[lane], vb = r0[lane + 8];
        uint4 wa = r1[lane], wb = r1[lane + 8];
        __half2* ha = (__half2*)&va;
        __half2* hb = (__half2*)&vb;
        const __half2* ka = (const __half2*)&wa;
        const __half2* kb = (const __half2*)&wb;
        #pragma unroll
        for (int q = 0; q < 4; q++) {        // pair-sum in fp16 (in-place)
            ha[q] = __hadd2(ha[q], ka[q]);
            hb[q] = __hadd2(hb[q], kb[q]);
        }
        #pragma unroll
        for (int q = 0; q < 4; q++) {        // fp32 accumulate
            acc[2*q]     += __low2float(ha[q]);
            acc[2*q+1]   += __high2float(ha[q]);
            acc[8+2*q]   += __low2float(hb[q]);
            acc[8+2*q+1] += __high2float(hb[q]);
        }
    }
    if (j < c) {
        int s0 = g_epack[off + j];
        const uint4* r0 = (const uint4*)(srcp + (size_t)s0 * 128);
        uint4 va = r0[lane], vb = r0[lane + 8];
        const __half2* ha = (const __half2*)&va;
        const __half2* hb = (const __half2*)&vb;
        #pragma unroll
        for (int q = 0; q < 4; q++) {
            acc[2*q]     += __low2float(ha[q]);
            acc[2*q+1]   += __high2float(ha[q]);
            acc[8+2*q]   += __low2float(hb[q]);
            acc[8+2*q+1] += __high2float(hb[q]);
        }
    }

    if (c > 0) {                           // predicated skip: no store for c==0
        float w = 1.0f / (float)c;
        uint4 oa, ob;
        __half2* pa = (__half2*)&oa;
        __half2* pb = (__half2*)&ob;
        #pragma unroll
        for (int q = 0; q < 4; q++) {
            pa[q] = __floats2half2_rn(acc[2*q] * w, acc[2*q+1] * w);
            pb[q] = __floats2half2_rn(acc[8+2*q] * w, acc[8+2*q+1] * w);
        }
        __half* dstp = (SRC == 0) ? g_xagg1 : g_xagg2;
        ((uint4*)(dstp + (size_t)seg * 128))[lane] = oa;
        ((uint4*)(dstp + (size_t)seg * 128))[lane + 8] = ob;
    }

    if (SRC == 1 && lane == 0 && c > 0) g_cnt[seg] = 0;   // restore for replay
}

// ---------------- GEMM: out[m,:] = A[m,0:1152] @ Wstack + bias ----------------
// Single fp16 product both layers. L1 epilogue: relu -> g_hf; L2: sigmoid -> out.
template <int FOUT, int LAYER>
__global__ void __launch_bounds__(256)
mm_kernel(const float* __restrict__ bias, float* __restrict__ outExt, int M) {
    constexpr int WN = (FOUT == 128) ? 64 : 32;
    constexpr int NFR = WN / 8;
    constexpr int TB = 128;                 // bytes per smem row (64 fp16)
    constexpr int ABYT = 128 * TB;          // 16 KB
    constexpr int BBYT = FOUT * TB;         // 16 or 8 KB
    constexpr int STAGE = ABYT + BBYT;
    constexpr int NCHUNK = 18;

    extern __shared__ char smem[];
    const unsigned sbase = smem_u32(smem);

    const __half* wb = (LAYER == 1) ? g_wb1 : g_wb2;

    const int tid = threadIdx.x;
    const int wid = tid >> 5, lane = tid & 31;
    const int wm = wid & 3, wn = wid >> 2;
    const int g = lane >> 2, t = lane & 3;
    const int m0 = blockIdx.x * 128;

    float acc[2][NFR][4];
    #pragma unroll
    for (int mi = 0; mi < 2; mi++)
        #pragma unroll
        for (int ni = 0; ni < NFR; ni++)
            #pragma unroll
            for (int q = 0; q < 4; q++) acc[mi][ni][q] = 0.f;

    auto load_chunk = [&](int c, int s) {
        const unsigned a0 = sbase + s * STAGE;
        const unsigned b0 = a0 + ABYT;
        #pragma unroll
        for (int i = 0; i < 4; i++) {
            int idx = tid + i * 256;
            int row = idx >> 3, t16 = idx & 7;
            const __half* s0;
            size_t go;
            if (c < 16) {
                s0 = (LAYER == 1) ? g_xagg1 : g_xagg2;
                go = (size_t)(m0 + row) * 1024 + c * 64 + t16 * 8;
            } else {
                s0 = (LAYER == 1) ? g_xf : g_hf;
                go = (size_t)(m0 + row) * 128 + (c - 16) * 64 + t16 * 8;
            }
            unsigned d = a0 + row * TB + ((t16 * 16) ^ ((row & 7) * 16));
            cp16(d, s0 + go);
        }
        #pragma unroll
        for (int i = 0; i < FOUT / 32; i++) {
            int idx = tid + i * 256;
            int row = idx >> 3, t16 = idx & 7;
            size_t go = (size_t)row * 1152 + c * 64 + t16 * 8;
            unsigned d = b0 + row * TB + ((t16 * 16) ^ ((row & 7) * 16));
            cp16(d, wb + go);
        }
    };

    load_chunk(0, 0);
    CP_COMMIT();

    #pragma unroll 1
    for (int c = 0; c < NCHUNK; c++) {
        if (c < NCHUNK - 1) {
            load_chunk(c + 1, (c + 1) & 1);
            CP_COMMIT();
            CP_WAIT(1);
        } else {
            CP_WAIT(0);
        }
        __syncthreads();

        const int s = c & 1;
        const unsigned sA = sbase + s * STAGE;
        const unsigned sB = sA + ABYT;

        #pragma unroll
        for (int ks = 0; ks < 4; ks++) {
            const int kb = ks * 32 + t * 4;
            unsigned ah[2][4], bh[NFR][2];
            #pragma unroll
            for (int mi = 0; mi < 2; mi++) {
                int r0 = wm * 32 + mi * 16 + g;
                int r1 = r0 + 8;
                unsigned o00 = r0 * TB + (kb ^ ((r0 & 7) * 16));
                unsigned o10 = r1 * TB + (kb ^ ((r1 & 7) * 16));
                unsigned o01 = r0 * TB + ((kb + 16) ^ ((r0 & 7) * 16));
                unsigned o11 = r1 * TB + ((kb + 16) ^ ((r1 & 7) * 16));
                ah[mi][0] = lds32(sA + o00); ah[mi][1] = lds32(sA + o10);
                ah[mi][2] = lds32(sA + o01); ah[mi][3] = lds32(sA + o11);
            }
            #pragma unroll
            for (int ni = 0; ni < NFR; ni++) {
                int nr = wn * WN + ni * 8 + g;
                unsigned o0 = nr * TB + (kb ^ ((nr & 7) * 16));
                unsigned o1 = nr * TB + ((kb + 16) ^ ((nr & 7) * 16));
                bh[ni][0] = lds32(sB + o0); bh[ni][1] = lds32(sB + o1);
            }
            #pragma unroll
            for (int mi = 0; mi < 2; mi++)
                #pragma unroll
                for (int ni = 0; ni < NFR; ni++)
                    mma_fp16(acc[mi][ni], ah[mi], bh[ni]);
        }
        __syncthreads();
    }

    // -------- epilogue --------
    #pragma unroll
    for (int mi = 0; mi < 2; mi++) {
        int row0 = m0 + wm * 32 + mi * 16 + g;
        #pragma unroll
        for (int ni = 0; ni < NFR; ni++) {
            int col = wn * WN + ni * 8 + 2 * t;
            float b0 = bias[col], b1 = bias[col + 1];
            float v[4] = {acc[mi][ni][0] + b0, acc[mi][ni][1] + b1,
                          acc[mi][ni][2] + b0, acc[mi][ni][3] + b1};
            if (LAYER == 1) {
                #pragma unroll
                for (int q = 0; q < 4; q++) v[q] = fmaxf(v[q], 0.f);
                if (row0 < M)
                    *(__half2*)(g_hf + (size_t)row0 * 128 + col) =
                        __floats2half2_rn(v[0], v[1]);
                if (row0 + 8 < M)
                    *(__half2*)(g_hf + (size_t)(row0 + 8) * 128 + col) =
                        __floats2half2_rn(v[2], v[3]);
            } else {
                #pragma unroll
                for (int q = 0; q < 4; q++) v[q] = 1.0f / (1.0f + expf(-v[q]));
                if (row0 < M)
                    *(float2*)(outExt + (size_t)row0 * FOUT + col) = make_float2(v[0], v[1]);
                if (row0 + 8 < M)
                    *(float2*)(outExt + (size_t)(row0 + 8) * FOUT + col) = make_float2(v[2], v[3]);
            }
        }
    }
}

// ---------------- launch ----------------
extern "C" void kernel_launch(void* const* d_in, const int* in_sizes, int n_in,
                              void* d_out, int out_size) {
    const float* x     = (const float*)d_in[0];
    const void*  ei    = d_in[1];
    const void*  et    = d_in[2];
    const float* W1    = (const float*)d_in[3];
    const float* root1 = (const float*)d_in[4];
    const float* b1    = (const float*)d_in[5];
    const float* W2    = (const float*)d_in[6];
    const float* root2 = (const float*)d_in[7];
    const float* b2    = (const float*)d_in[8];
    float* out = (float*)d_out;

    const int M = in_sizes[0] / 128;   // 50000
    const int E = in_sizes[2];         // 500000
    const int n8 = M * 8;
    const int n4 = n8 / 4;             // 400000 divisible by 4

    const int SM1 = 2 * (16384 + 16384);  // 64 KB
    const int SM2 = 2 * (16384 + 8192);   // 48 KB
    static int configured = 0;
    if (!configured) {
        cudaFuncSetAttribute((const void*)&mm_kernel<128, 1>,
                             cudaFuncAttributeMaxDynamicSharedMemorySize, SM1);
        cudaFuncSetAttribute((const void*)&mm_kernel<64, 2>,
                             cudaFuncAttributeMaxDynamicSharedMemorySize, SM2);
        configured = 1;
    }

    // ---- launch 1: count + conv1 + W pack ----
    const int CNT  = (E + 255) / 256;
    const int CONV = (M * 32 + 255) / 256;
    const int PACK = (128 * 1152 + 64 * 1152 + 255) / 256;
    stage1_kernel<<<CNT + CONV + PACK, 256>>>(ei, et, x, W1, root1, W2, root2, E, M);

    // ---- CSR offsets + fill ----
    off_kernel<<<(n4 + 255) / 256, 256>>>(n4);
    fill_kernel<<<(E + 255) / 256, 256>>>(ei, et, E);

    const int mblocks = (M + 127) / 128;
    const int ablocks = (n8 * 8 + 255) / 256;   // 8 lanes per segment

    // ---- layer 1 ----
    agg_kernel<0><<<ablocks, 256>>>(n8);
    mm_kernel<128, 1><<<mblocks, 256, SM1>>>(b1, nullptr, M);

    // ---- layer 2 ----
    agg_kernel<1><<<ablocks, 256>>>(n8);
    mm_kernel<64, 2><<<mblocks, 256, SM2>>>(b2, out, M);
}